// round 12
// baseline (speedup 1.0000x reference)
#include <cuda_runtime.h>
#include <cuda_fp16.h>
#include <cstdint>

#define CC   128
#define HWN  4096
#define BN   8
#define BQ   128          // queries per CTA
#define BK   64           // keys per tile
#define NIT  (HWN / BK)   // 64

// scratch
__device__ float  g_qres[(size_t)BN * CC * HWN];  // q proj fp32 [b][c][p] (residual, output layout)
__device__ __half g_qh[(size_t)BN * HWN * CC];    // q proj fp16 [b][p][c]
__device__ __half g_kh[(size_t)BN * HWN * CC];    // k proj fp16 [b][p][c]
__device__ __half g_vh[(size_t)BN * CC * HWN];    // value fp16 [b][c][hw]

// ---------------------------------------------------------------------------
// helpers
// ---------------------------------------------------------------------------
__device__ __forceinline__ uint32_t s2u(const void* p) {
    uint32_t a;
    asm("{ .reg .u64 t; cvta.to.shared.u64 t, %1; cvt.u32.u64 %0, t; }" : "=r"(a) : "l"(p));
    return a;
}
__device__ __forceinline__ void ldsm4(uint32_t* a, uint32_t addr) {
    asm volatile("ldmatrix.sync.aligned.m8n8.x4.shared.b16 {%0,%1,%2,%3},[%4];"
                 : "=r"(a[0]), "=r"(a[1]), "=r"(a[2]), "=r"(a[3]) : "r"(addr));
}
__device__ __forceinline__ void ldsm4t(uint32_t* a, uint32_t addr) {
    asm volatile("ldmatrix.sync.aligned.m8n8.x4.trans.shared.b16 {%0,%1,%2,%3},[%4];"
                 : "=r"(a[0]), "=r"(a[1]), "=r"(a[2]), "=r"(a[3]) : "r"(addr));
}
__device__ __forceinline__ void mma16816(float* d, const uint32_t* a, const uint32_t* b) {
    asm volatile("mma.sync.aligned.m16n8k16.row.col.f32.f16.f16.f32 "
                 "{%0,%1,%2,%3},{%4,%5,%6,%7},{%8,%9},{%0,%1,%2,%3};"
                 : "+f"(d[0]), "+f"(d[1]), "+f"(d[2]), "+f"(d[3])
                 : "r"(a[0]), "r"(a[1]), "r"(a[2]), "r"(a[3]), "r"(b[0]), "r"(b[1]));
}
// fp16-accumulator variant: d = 2 regs (4 halfs)
__device__ __forceinline__ void mma16816h(uint32_t* d, const uint32_t* a, const uint32_t* b) {
    asm volatile("mma.sync.aligned.m16n8k16.row.col.f16.f16.f16.f16 "
                 "{%0,%1},{%2,%3,%4,%5},{%6,%7},{%0,%1};"
                 : "+r"(d[0]), "+r"(d[1])
                 : "r"(a[0]), "r"(a[1]), "r"(a[2]), "r"(a[3]), "r"(b[0]), "r"(b[1]));
}
__device__ __forceinline__ uint32_t packh2(float x, float y) {
    __half2 h = __floats2half2_rn(x, y);
    return *(uint32_t*)&h;
}
__device__ __forceinline__ float ex2f(float x) {
    float r;
    asm("ex2.approx.f32 %0, %1;" : "=f"(r) : "f"(x));
    return r;
}

#define CP_A16(dst, src) asm volatile("cp.async.cg.shared.global [%0], [%1], 16;" :: "r"(dst), "l"(src))
#define CP_COMMIT()      asm volatile("cp.async.commit_group;" ::: "memory")
#define CP_WAIT(n)       asm volatile("cp.async.wait_group %0;" :: "n"(n) : "memory")

// ---------------------------------------------------------------------------
// Projection on tensor cores: D[o][p] = sum_c W[o][c] * X[c][p]  (+bias)
// grid (HWN/128, BN, 3), 256 threads. z=0: q proj, z=1: k proj, z=2: V fp32->fp16.
// ---------------------------------------------------------------------------
#define PSM_BYTES (2 * 128 * 136 * 2)   // 69632: Xh + Wh (reused for staging)

__global__ void __launch_bounds__(256) proj_kernel(
    const float* __restrict__ q_img, const float* __restrict__ k_img,
    const float* __restrict__ value,
    const float* __restrict__ Wq, const float* __restrict__ bq,
    const float* __restrict__ Wk, const float* __restrict__ bk)
{
    extern __shared__ __align__(16) char psm[];

    // ---- z == 2: V conversion (pure streaming), overlapped with projections ----
    if (blockIdx.z == 2) {
        const int nth = 32 * 8 * 256;
        int tid = (blockIdx.y * 32 + blockIdx.x) * 256 + threadIdx.x;
        const float4* vin = (const float4*)value;
        __half2* o = (__half2*)g_vh;
        #pragma unroll 4
        for (size_t i = tid; i < (size_t)BN * CC * HWN / 4; i += nth) {
            float4 f = vin[i];
            o[2 * i]     = __floats2half2_rn(f.x, f.y);
            o[2 * i + 1] = __floats2half2_rn(f.z, f.w);
        }
        return;
    }

    __half* Xh  = (__half*)psm;            // [128 c][136] (p fast)
    __half* Wh  = Xh + 128 * 136;          // [128 o][136] (c fast)
    float*  Os  = (float*)psm;             // reuse: [128 o][132] (p fast)
    __half* Osh = (__half*)psm;            // reuse: [128 p][136] (o fast)
    __shared__ float biass[128];

    const bool isQ = (blockIdx.z == 0);
    const float* in   = isQ ? q_img : k_img;
    const float* W    = isQ ? Wq : Wk;
    const float* bias = isQ ? bq : bk;

    const int b  = blockIdx.y;
    const int p0 = blockIdx.x * 128;
    const int t  = threadIdx.x;
    const int w  = t >> 5, l = t & 31;

    const float* inb = in + (size_t)b * CC * HWN;

    // load X [c][p] fp32 -> fp16 smem (rows c, 128 p halfs + pad)
    #pragma unroll
    for (int it = 0; it < 16; it++) {
        int idx = it * 256 + t, c = idx >> 5, f4 = idx & 31;
        float4 v = *(const float4*)(inb + c * HWN + p0 + f4 * 4);
        uint2 h; h.x = packh2(v.x, v.y); h.y = packh2(v.z, v.w);
        *(uint2*)&Xh[c * 136 + f4 * 4] = h;
    }
    // load W [o][c] fp32 -> fp16
    #pragma unroll
    for (int it = 0; it < 16; it++) {
        int idx = it * 256 + t, o = idx >> 5, f4 = idx & 31;
        float4 v = *(const float4*)(W + o * 128 + f4 * 4);
        uint2 h; h.x = packh2(v.x, v.y); h.y = packh2(v.z, v.w);
        *(uint2*)&Wh[o * 136 + f4 * 4] = h;
    }
    if (t < 128) biass[t] = bias[t];
    __syncthreads();

    const uint32_t sb = s2u(psm);
    const uint32_t aW = sb + (uint32_t)(128 * 136 + (w * 16 + (l & 15)) * 136 + (l >> 4) * 8) * 2;
    const uint32_t bX = sb + (uint32_t)((((l & 7) + ((l >> 3) & 1) * 8)) * 136 + ((l >> 4) & 1) * 8) * 2;

    float acc[16][4];
    #pragma unroll
    for (int n = 0; n < 16; n++)
        #pragma unroll
        for (int e = 0; e < 4; e++) acc[n][e] = 0.f;

    #pragma unroll
    for (int ks = 0; ks < 8; ks++) {
        uint32_t A[4];
        ldsm4(A, aW + ks * 32);
        #pragma unroll
        for (int nt2 = 0; nt2 < 8; nt2++) {
            uint32_t Bf[4];
            ldsm4t(Bf, bX + (uint32_t)(ks * 16 * 136 + nt2 * 16) * 2);
            mma16816(acc[2 * nt2],     A, Bf);
            mma16816(acc[2 * nt2 + 1], A, Bf + 2);
        }
    }

    const int o1 = w * 16 + (l >> 2), o2 = o1 + 8;
    const float b1 = biass[o1], b2 = biass[o2];
    #pragma unroll
    for (int n = 0; n < 16; n++) {
        acc[n][0] += b1; acc[n][1] += b1;
        acc[n][2] += b2; acc[n][3] += b2;
    }
    __syncthreads();   // done with Xh/Wh

    if (isQ) {
        // fp32 residual, [o][p] staging -> g_qres coalesced
        #pragma unroll
        for (int n = 0; n < 16; n++) {
            int p = n * 8 + 2 * (l & 3);
            *(float2*)&Os[o1 * 132 + p] = make_float2(acc[n][0], acc[n][1]);
            *(float2*)&Os[o2 * 132 + p] = make_float2(acc[n][2], acc[n][3]);
        }
        __syncthreads();
        float* qres = g_qres + (size_t)b * CC * HWN;
        #pragma unroll
        for (int it = 0; it < 64; it++) {
            int idx = it * 256 + t, o = idx >> 7, p = idx & 127;
            qres[(size_t)o * HWN + p0 + p] = Os[o * 132 + p];
        }
        __syncthreads();
    }

    // fp16 token-major [p][o] staging -> g_qh/g_kh coalesced
    #pragma unroll
    for (int n = 0; n < 16; n++) {
        int p = n * 8 + 2 * (l & 3);
        Osh[p * 136 + o1]       = __float2half(acc[n][0]);
        Osh[(p + 1) * 136 + o1] = __float2half(acc[n][1]);
        Osh[p * 136 + o2]       = __float2half(acc[n][2]);
        Osh[(p + 1) * 136 + o2] = __float2half(acc[n][3]);
    }
    __syncthreads();
    __half* outh = (isQ ? g_qh : g_kh) + (size_t)b * HWN * CC + (size_t)p0 * CC;
    #pragma unroll
    for (int it = 0; it < 32; it++) {
        int idx = it * 256 + t, p = idx >> 6, h2 = idx & 63;
        *(uint32_t*)(outh + (size_t)p * CC + 2 * h2) = *(uint32_t*)&Osh[p * 136 + 2 * h2];
    }
}

// ---------------------------------------------------------------------------
// attn SMEM (half units): Q [128][136] persistent + 2 x {K 64x136, V 128x72}
// ---------------------------------------------------------------------------
#define QROW 136
#define KROW 136
#define VROW 72
#define KS_OFF(buf) (128 * QROW + (buf) * 64 * KROW)
#define VS_OFF(buf) (128 * QROW + 2 * 64 * KROW + (buf) * 128 * VROW)
#define SMEM_HALFS  (128 * QROW + 2 * 64 * KROW + 2 * 128 * VROW)   // 53248
#define SMEM_BYTES  (SMEM_HALFS * 2)                                 // 106496

__device__ __forceinline__ void load_kv(uint32_t sb, int t,
                                        const __half* kh, const __half* vh,
                                        int tile, int buf)
{
    #pragma unroll
    for (int i = 0; i < 4; i++) {       // K tile: 64 rows x 256B
        int idx = i * 256 + t, r = idx >> 4, c = idx & 15;
        CP_A16(sb + (uint32_t)(KS_OFF(buf) + r * KROW) * 2 + c * 16,
               kh + (size_t)(tile * BK + r) * CC + c * 8);
    }
    #pragma unroll
    for (int i = 0; i < 4; i++) {       // V tile: 128 rows(c) x 128B
        int idx = i * 256 + t, r = idx >> 3, c = idx & 7;
        CP_A16(sb + (uint32_t)(VS_OFF(buf) + r * VROW) * 2 + c * 16,
               vh + (size_t)r * HWN + tile * BK + c * 8);
    }
}

// exp scale: S * (1/64) * log2(e), applied as single FMUL before ex2
#define EX2SCALE 0.0225421993f

// ---------------------------------------------------------------------------
// Flash attention, fp16 mma.sync, KEY-SPLIT warps.
// grid (32, 8), 256 threads (8 warps). warp w: m-block mb=w>>1 (32 q rows),
// key-half kh2=w&1 (32 of 64 keys). Each warp accumulates partial O/l over
// its key half; partials are reduced once in the epilogue.
// ---------------------------------------------------------------------------
__global__ void __launch_bounds__(256, 2)
attn_kernel(float* __restrict__ out)
{
    extern __shared__ __align__(16) __half smh[];
    const uint32_t sb = s2u(smh);
    const int t = threadIdx.x, w = t >> 5, l = t & 31;
    const int mb = w >> 1, kh2 = w & 1;
    const int b = blockIdx.y, q0 = blockIdx.x * BQ;

    const __half* qh = g_qh + (size_t)b * HWN * CC + (size_t)q0 * CC;
    const __half* kh = g_kh + (size_t)b * HWN * CC;
    const __half* vh = g_vh + (size_t)b * CC * HWN;

    // prologue: Q persistent + K/V stages 0,1
    #pragma unroll
    for (int i = 0; i < 8; i++) {
        int idx = i * 256 + t, r = idx >> 4, c = idx & 15;
        CP_A16(sb + (uint32_t)(r * QROW) * 2 + c * 16, qh + (size_t)r * CC + c * 8);
    }
    load_kv(sb, t, kh, vh, 0, 0);
    CP_COMMIT();
    load_kv(sb, t, kh, vh, 1, 1);
    CP_COMMIT();

    // per-lane bases
    const uint32_t aQ0 = sb + (uint32_t)((mb * 32 + (l & 15)) * QROW + (l >> 4) * 8) * 2;
    const uint32_t aQ1 = aQ0 + (uint32_t)(16 * QROW) * 2;
    const uint32_t bKrel = (uint32_t)(((l & 7) + ((l >> 4) & 1) * 8 + kh2 * 32) * KROW + ((l >> 3) & 1) * 8) * 2;
    const uint32_t bVrel = (uint32_t)(((l & 7) + ((l >> 4) & 1) * 8) * VROW + ((l >> 3) & 1) * 8 + kh2 * 32) * 2;

    // partial O (fp16 accum) over this warp's key half
    uint32_t O[2][16][2];
    #pragma unroll
    for (int m = 0; m < 2; m++)
        #pragma unroll
        for (int n = 0; n < 16; n++) { O[m][n][0] = 0u; O[m][n][1] = 0u; }
    float lac[2][2] = {{0.f, 0.f}, {0.f, 0.f}};

    for (int j = 0; j < NIT; j++) {
        if (j + 1 < NIT) CP_WAIT(1); else CP_WAIT(0);
        __syncthreads();
        const int buf = j & 1;
        const uint32_t kbb = sb + (uint32_t)KS_OFF(buf) * 2 + bKrel;
        const uint32_t vbb = sb + (uint32_t)VS_OFF(buf) * 2 + bVrel;

        // ---- S over this warp's 32 keys: 8 independent fp16 chains ----
        uint32_t S4[2][4][2];           // [ms][kf*2+sub][reg]
        #pragma unroll
        for (int m = 0; m < 2; m++)
            #pragma unroll
            for (int n = 0; n < 4; n++) { S4[m][n][0] = 0u; S4[m][n][1] = 0u; }

        #pragma unroll
        for (int ks = 0; ks < 8; ks++) {
            uint32_t A0[4], A1[4], B0[4], B1[4];
            ldsm4(A0, aQ0 + ks * 32);
            ldsm4(A1, aQ1 + ks * 32);
            ldsm4(B0, kbb + (uint32_t)(ks * 16) * 2);                 // keys +0..15
            ldsm4(B1, kbb + (uint32_t)(16 * KROW + ks * 16) * 2);     // keys +16..31
            mma16816h(S4[0][0], A0, B0);
            mma16816h(S4[0][1], A0, B0 + 2);
            mma16816h(S4[0][2], A0, B1);
            mma16816h(S4[0][3], A0, B1 + 2);
            mma16816h(S4[1][0], A1, B0);
            mma16816h(S4[1][1], A1, B0 + 2);
            mma16816h(S4[1][2], A1, B1);
            mma16816h(S4[1][3], A1, B1 + 2);
        }

        // ---- exp + PV per 16-key group ----
        #pragma unroll
        for (int kf = 0; kf < 2; kf++) {
            uint32_t P[2][4];
            #pragma unroll
            for (int m = 0; m < 2; m++) {
                float2 a0 = __half22float2(*(__half2*)&S4[m][kf * 2][0]);      // r1 lo
                float2 a1 = __half22float2(*(__half2*)&S4[m][kf * 2][1]);      // r2 lo
                float2 b0 = __half22float2(*(__half2*)&S4[m][kf * 2 + 1][0]);  // r1 hi
                float2 b1 = __half22float2(*(__half2*)&S4[m][kf * 2 + 1][1]);  // r2 hi
                float p0 = ex2f(a0.x * EX2SCALE), p1 = ex2f(a0.y * EX2SCALE);
                float p2 = ex2f(a1.x * EX2SCALE), p3 = ex2f(a1.y * EX2SCALE);
                float p4 = ex2f(b0.x * EX2SCALE), p5 = ex2f(b0.y * EX2SCALE);
                float p6 = ex2f(b1.x * EX2SCALE), p7 = ex2f(b1.y * EX2SCALE);
                P[m][0] = packh2(p0, p1);
                P[m][1] = packh2(p2, p3);
                P[m][2] = packh2(p4, p5);
                P[m][3] = packh2(p6, p7);
                lac[m][0] += (p0 + p1) + (p4 + p5);
                lac[m][1] += (p2 + p3) + (p6 + p7);
            }
            #pragma unroll
            for (int np = 0; np < 8; np++) {
                uint32_t Bf[4];
                ldsm4(Bf, vbb + (uint32_t)(np * 16 * VROW + kf * 16) * 2);
                mma16816h(O[0][2 * np],     P[0], Bf);
                mma16816h(O[0][2 * np + 1], P[0], Bf + 2);
                mma16816h(O[1][2 * np],     P[1], Bf);
                mma16816h(O[1][2 * np + 1], P[1], Bf + 2);
            }
        }

        __syncthreads();
        if (j + 2 < NIT) { load_kv(sb, t, kh, vh, j + 2, buf); CP_COMMIT(); }
    }

    // ---- epilogue: reduce key-half partials, divide by total l, add residual ----
    // quad-reduce l partials (each covers this warp's 32 keys)
    #pragma unroll
    for (int m = 0; m < 2; m++)
        #pragma unroll
        for (int r = 0; r < 2; r++) {
            lac[m][r] += __shfl_xor_sync(0xffffffffu, lac[m][r], 1);
            lac[m][r] += __shfl_xor_sync(0xffffffffu, lac[m][r], 2);
        }

    __syncthreads();                    // all warps done with smem
    float* Osc   = (float*)smh;         // [128 c][129 p]
    float* lpart = Osc + 128 * 129;     // [2][128]
    float* linv  = lpart + 2 * 128;     // [128]

    // write l partials (quad leaders)
    if ((l & 3) == 0) {
        #pragma unroll
        for (int m = 0; m < 2; m++) {
            int r1 = mb * 32 + m * 16 + (l >> 2);
            lpart[kh2 * 128 + r1]     = lac[m][0];
            lpart[kh2 * 128 + r1 + 8] = lac[m][1];
        }
    }
    // key-half 0 warps write their partial O
    if (kh2 == 0) {
        #pragma unroll
        for (int m = 0; m < 2; m++) {
            const int p1 = mb * 32 + m * 16 + (l >> 2), p2 = p1 + 8;
            #pragma unroll
            for (int nt = 0; nt < 16; nt++) {
                int c = nt * 8 + 2 * (l & 3);
                float2 lo = __half22float2(*(__half2*)&O[m][nt][0]);
                float2 hi = __half22float2(*(__half2*)&O[m][nt][1]);
                Osc[c * 129 + p1]       = lo.x;
                Osc[(c + 1) * 129 + p1] = lo.y;
                Osc[c * 129 + p2]       = hi.x;
                Osc[(c + 1) * 129 + p2] = hi.y;
            }
        }
    }
    __syncthreads();
    // key-half 1 warps add their partial O; first 128 threads build 1/l
    if (kh2 == 1) {
        #pragma unroll
        for (int m = 0; m < 2; m++) {
            const int p1 = mb * 32 + m * 16 + (l >> 2), p2 = p1 + 8;
            #pragma unroll
            for (int nt = 0; nt < 16; nt++) {
                int c = nt * 8 + 2 * (l & 3);
                float2 lo = __half22float2(*(__half2*)&O[m][nt][0]);
                float2 hi = __half22float2(*(__half2*)&O[m][nt][1]);
                Osc[c * 129 + p1]       += lo.x;
                Osc[(c + 1) * 129 + p1] += lo.y;
                Osc[c * 129 + p2]       += hi.x;
                Osc[(c + 1) * 129 + p2] += hi.y;
            }
        }
    }
    if (t < 128) linv[t] = 1.f / (lpart[t] + lpart[128 + t]);
    __syncthreads();

    const float* qres = g_qres + (size_t)b * CC * HWN + q0;
    float* ob = out + (size_t)b * CC * HWN + q0;
    #pragma unroll
    for (int it = 0; it < 64; it++) {
        int idx = it * 256 + t, c = idx >> 7, p = idx & 127;
        ob[(size_t)c * HWN + p] = Osc[c * 129 + p] * linv[p] + qres[(size_t)c * HWN + p];
    }
}

// ---------------------------------------------------------------------------
extern "C" void kernel_launch(void* const* d_in, const int* in_sizes, int n_in,
                              void* d_out, int out_size)
{
    const float* query = (const float*)d_in[0];
    const float* key   = (const float*)d_in[1];
    const float* value = (const float*)d_in[2];
    const float* Wq    = (const float*)d_in[3];
    const float* bq    = (const float*)d_in[4];
    const float* Wk    = (const float*)d_in[5];
    const float* bk    = (const float*)d_in[6];
    float* out = (float*)d_out;

    cudaFuncSetAttribute(proj_kernel, cudaFuncAttributeMaxDynamicSharedMemorySize, PSM_BYTES);
    cudaFuncSetAttribute(attn_kernel, cudaFuncAttributeMaxDynamicSharedMemorySize, SMEM_BYTES);

    dim3 pgrid(HWN / 128, BN, 3);
    proj_kernel<<<pgrid, 256, PSM_BYTES>>>(query, key, value, Wq, bq, Wk, bk);

    dim3 agrid(HWN / BQ, BN);
    attn_kernel<<<agrid, 256, SMEM_BYTES>>>(out);
}

// round 13
// speedup vs baseline: 1.0584x; 1.0584x over previous
#include <cuda_runtime.h>
#include <cuda_fp16.h>
#include <cstdint>

#define CC   128
#define HWN  4096
#define BN   8
#define BQ   128          // queries per CTA
#define BK   64           // keys per tile
#define NIT  (HWN / BK)   // 64

// scratch
__device__ float  g_qres[(size_t)BN * CC * HWN];  // q proj fp32 [b][c][p] (residual, output layout)
__device__ __half g_qh[(size_t)BN * HWN * CC];    // q proj fp16 [b][p][c]
__device__ __half g_kh[(size_t)BN * HWN * CC];    // k proj fp16 [b][p][c]
__device__ __half g_vh[(size_t)BN * CC * HWN];    // value fp16 [b][c][hw]

// ---------------------------------------------------------------------------
// helpers
// ---------------------------------------------------------------------------
__device__ __forceinline__ uint32_t s2u(const void* p) {
    uint32_t a;
    asm("{ .reg .u64 t; cvta.to.shared.u64 t, %1; cvt.u32.u64 %0, t; }" : "=r"(a) : "l"(p));
    return a;
}
__device__ __forceinline__ void ldsm4(uint32_t* a, uint32_t addr) {
    asm volatile("ldmatrix.sync.aligned.m8n8.x4.shared.b16 {%0,%1,%2,%3},[%4];"
                 : "=r"(a[0]), "=r"(a[1]), "=r"(a[2]), "=r"(a[3]) : "r"(addr));
}
__device__ __forceinline__ void ldsm4t(uint32_t* a, uint32_t addr) {
    asm volatile("ldmatrix.sync.aligned.m8n8.x4.trans.shared.b16 {%0,%1,%2,%3},[%4];"
                 : "=r"(a[0]), "=r"(a[1]), "=r"(a[2]), "=r"(a[3]) : "r"(addr));
}
__device__ __forceinline__ void mma16816(float* d, const uint32_t* a, const uint32_t* b) {
    asm volatile("mma.sync.aligned.m16n8k16.row.col.f32.f16.f16.f32 "
                 "{%0,%1,%2,%3},{%4,%5,%6,%7},{%8,%9},{%0,%1,%2,%3};"
                 : "+f"(d[0]), "+f"(d[1]), "+f"(d[2]), "+f"(d[3])
                 : "r"(a[0]), "r"(a[1]), "r"(a[2]), "r"(a[3]), "r"(b[0]), "r"(b[1]));
}
// fp16-accumulator variant: d = 2 regs (4 halfs)
__device__ __forceinline__ void mma16816h(uint32_t* d, const uint32_t* a, const uint32_t* b) {
    asm volatile("mma.sync.aligned.m16n8k16.row.col.f16.f16.f16.f16 "
                 "{%0,%1},{%2,%3,%4,%5},{%6,%7},{%0,%1};"
                 : "+r"(d[0]), "+r"(d[1])
                 : "r"(a[0]), "r"(a[1]), "r"(a[2]), "r"(a[3]), "r"(b[0]), "r"(b[1]));
}
__device__ __forceinline__ uint32_t packh2(float x, float y) {
    __half2 h = __floats2half2_rn(x, y);
    return *(uint32_t*)&h;
}
__device__ __forceinline__ float ex2f(float x) {
    float r;
    asm("ex2.approx.f32 %0, %1;" : "=f"(r) : "f"(x));
    return r;
}

#define CP_A16(dst, src) asm volatile("cp.async.cg.shared.global [%0], [%1], 16;" :: "r"(dst), "l"(src))
#define CP_COMMIT()      asm volatile("cp.async.commit_group;" ::: "memory")
#define CP_WAIT(n)       asm volatile("cp.async.wait_group %0;" :: "n"(n) : "memory")

// ---------------------------------------------------------------------------
// Projection on tensor cores: D[o][p] = sum_c W[o][c] * X[c][p]  (+bias)
// grid (HWN/128, BN, 3), 256 threads. z=0: q proj, z=1: k proj, z=2: V fp32->fp16.
// ---------------------------------------------------------------------------
#define PSM_BYTES (2 * 128 * 136 * 2)   // 69632: Xh + Wh (reused for staging)

__global__ void __launch_bounds__(256) proj_kernel(
    const float* __restrict__ q_img, const float* __restrict__ k_img,
    const float* __restrict__ value,
    const float* __restrict__ Wq, const float* __restrict__ bq,
    const float* __restrict__ Wk, const float* __restrict__ bk)
{
    extern __shared__ __align__(16) char psm[];

    // ---- z == 2: V conversion (pure streaming), overlapped with projections ----
    if (blockIdx.z == 2) {
        const int nth = 32 * 8 * 256;
        int tid = (blockIdx.y * 32 + blockIdx.x) * 256 + threadIdx.x;
        const float4* vin = (const float4*)value;
        __half2* o = (__half2*)g_vh;
        #pragma unroll 4
        for (size_t i = tid; i < (size_t)BN * CC * HWN / 4; i += nth) {
            float4 f = vin[i];
            o[2 * i]     = __floats2half2_rn(f.x, f.y);
            o[2 * i + 1] = __floats2half2_rn(f.z, f.w);
        }
        return;
    }

    __half* Xh  = (__half*)psm;            // [128 c][136] (p fast)
    __half* Wh  = Xh + 128 * 136;          // [128 o][136] (c fast)
    float*  Os  = (float*)psm;             // reuse: [128 o][132] (p fast)
    __half* Osh = (__half*)psm;            // reuse: [128 p][136] (o fast)
    __shared__ float biass[128];

    const bool isQ = (blockIdx.z == 0);
    const float* in   = isQ ? q_img : k_img;
    const float* W    = isQ ? Wq : Wk;
    const float* bias = isQ ? bq : bk;

    const int b  = blockIdx.y;
    const int p0 = blockIdx.x * 128;
    const int t  = threadIdx.x;
    const int w  = t >> 5, l = t & 31;

    const float* inb = in + (size_t)b * CC * HWN;

    // load X [c][p] fp32 -> fp16 smem (rows c, 128 p halfs + pad)
    #pragma unroll
    for (int it = 0; it < 16; it++) {
        int idx = it * 256 + t, c = idx >> 5, f4 = idx & 31;
        float4 v = *(const float4*)(inb + c * HWN + p0 + f4 * 4);
        uint2 h; h.x = packh2(v.x, v.y); h.y = packh2(v.z, v.w);
        *(uint2*)&Xh[c * 136 + f4 * 4] = h;
    }
    // load W [o][c] fp32 -> fp16
    #pragma unroll
    for (int it = 0; it < 16; it++) {
        int idx = it * 256 + t, o = idx >> 5, f4 = idx & 31;
        float4 v = *(const float4*)(W + o * 128 + f4 * 4);
        uint2 h; h.x = packh2(v.x, v.y); h.y = packh2(v.z, v.w);
        *(uint2*)&Wh[o * 136 + f4 * 4] = h;
    }
    if (t < 128) biass[t] = bias[t];
    __syncthreads();

    const uint32_t sb = s2u(psm);
    const uint32_t aW = sb + (uint32_t)(128 * 136 + (w * 16 + (l & 15)) * 136 + (l >> 4) * 8) * 2;
    const uint32_t bX = sb + (uint32_t)((((l & 7) + ((l >> 3) & 1) * 8)) * 136 + ((l >> 4) & 1) * 8) * 2;

    float acc[16][4];
    #pragma unroll
    for (int n = 0; n < 16; n++)
        #pragma unroll
        for (int e = 0; e < 4; e++) acc[n][e] = 0.f;

    #pragma unroll
    for (int ks = 0; ks < 8; ks++) {
        uint32_t A[4];
        ldsm4(A, aW + ks * 32);
        #pragma unroll
        for (int nt2 = 0; nt2 < 8; nt2++) {
            uint32_t Bf[4];
            ldsm4t(Bf, bX + (uint32_t)(ks * 16 * 136 + nt2 * 16) * 2);
            mma16816(acc[2 * nt2],     A, Bf);
            mma16816(acc[2 * nt2 + 1], A, Bf + 2);
        }
    }

    const int o1 = w * 16 + (l >> 2), o2 = o1 + 8;
    const float b1 = biass[o1], b2 = biass[o2];
    #pragma unroll
    for (int n = 0; n < 16; n++) {
        acc[n][0] += b1; acc[n][1] += b1;
        acc[n][2] += b2; acc[n][3] += b2;
    }
    __syncthreads();   // done with Xh/Wh

    if (isQ) {
        // fp32 residual, [o][p] staging -> g_qres coalesced
        #pragma unroll
        for (int n = 0; n < 16; n++) {
            int p = n * 8 + 2 * (l & 3);
            *(float2*)&Os[o1 * 132 + p] = make_float2(acc[n][0], acc[n][1]);
            *(float2*)&Os[o2 * 132 + p] = make_float2(acc[n][2], acc[n][3]);
        }
        __syncthreads();
        float* qres = g_qres + (size_t)b * CC * HWN;
        #pragma unroll
        for (int it = 0; it < 64; it++) {
            int idx = it * 256 + t, o = idx >> 7, p = idx & 127;
            qres[(size_t)o * HWN + p0 + p] = Os[o * 132 + p];
        }
        __syncthreads();
    }

    // fp16 token-major [p][o] staging -> g_qh/g_kh coalesced
    #pragma unroll
    for (int n = 0; n < 16; n++) {
        int p = n * 8 + 2 * (l & 3);
        Osh[p * 136 + o1]       = __float2half(acc[n][0]);
        Osh[(p + 1) * 136 + o1] = __float2half(acc[n][1]);
        Osh[p * 136 + o2]       = __float2half(acc[n][2]);
        Osh[(p + 1) * 136 + o2] = __float2half(acc[n][3]);
    }
    __syncthreads();
    __half* outh = (isQ ? g_qh : g_kh) + (size_t)b * HWN * CC + (size_t)p0 * CC;
    #pragma unroll
    for (int it = 0; it < 32; it++) {
        int idx = it * 256 + t, p = idx >> 6, h2 = idx & 63;
        *(uint32_t*)(outh + (size_t)p * CC + 2 * h2) = *(uint32_t*)&Osh[p * 136 + 2 * h2];
    }
}

// ---------------------------------------------------------------------------
// attn SMEM: 3 stages of {K 64x136, V 128x72} halfs. Q staged in stage 0
// during the prologue only (Q lives in registers afterwards).
// ---------------------------------------------------------------------------
#define KROW 136
#define VROW 72
#define STAGE_HALFS (64 * KROW + 128 * VROW)     // 17920
#define KS_OFF(s)   ((s) * STAGE_HALFS)
#define VS_OFF(s)   ((s) * STAGE_HALFS + 64 * KROW)
#define SMEM_HALFS  (3 * STAGE_HALFS)            // 53760
#define SMEM_BYTES  (SMEM_HALFS * 2)             // 107520

__device__ __forceinline__ void load_kv(uint32_t sb, int t,
                                        const __half* kh, const __half* vh,
                                        int tile, int s)
{
    #pragma unroll
    for (int i = 0; i < 4; i++) {       // K tile: 64 rows x 256B
        int idx = i * 256 + t, r = idx >> 4, c = idx & 15;
        CP_A16(sb + (uint32_t)(KS_OFF(s) + r * KROW) * 2 + c * 16,
               kh + (size_t)(tile * BK + r) * CC + c * 8);
    }
    #pragma unroll
    for (int i = 0; i < 4; i++) {       // V tile: 128 rows(c) x 128B
        int idx = i * 256 + t, r = idx >> 3, c = idx & 7;
        CP_A16(sb + (uint32_t)(VS_OFF(s) + r * VROW) * 2 + c * 16,
               vh + (size_t)r * HWN + tile * BK + c * 8);
    }
}

// exp scale: S * (1/64) * log2(e), applied as single FMUL before ex2
#define EX2SCALE 0.0225421993f

// ---------------------------------------------------------------------------
// Flash attention, fp16 mma.sync. grid (32, 8), 256 threads (8 warps x 16 rows)
// Round-10 structure: Q A-fragments register-resident; 3-stage cp.async, ONE
// barrier/iteration; 32-key halves with 4 independent chains. NEW: S also in
// fp16 accumulators (reg relief) + K B-fragments double-buffered across ks.
// ---------------------------------------------------------------------------
__global__ void __launch_bounds__(256, 2)
attn_kernel(float* __restrict__ out)
{
    extern __shared__ __align__(16) __half smh[];
    const uint32_t sb = s2u(smh);
    const int t = threadIdx.x, w = t >> 5, l = t & 31;
    const int b = blockIdx.y, q0 = blockIdx.x * BQ;

    const __half* qh = g_qh + (size_t)b * HWN * CC + (size_t)q0 * CC;
    const __half* kh = g_kh + (size_t)b * HWN * CC;
    const __half* vh = g_vh + (size_t)b * CC * HWN;

    // ---- prologue: stage Q in stage-0 region, hoist A-fragments to regs ----
    #pragma unroll
    for (int i = 0; i < 8; i++) {       // Q: 128 rows x 256B, row stride KROW halfs
        int idx = i * 256 + t, r = idx >> 4, c = idx & 15;
        CP_A16(sb + (uint32_t)(r * KROW) * 2 + c * 16, qh + (size_t)r * CC + c * 8);
    }
    CP_COMMIT();
    CP_WAIT(0);
    __syncthreads();

    uint32_t Aq[8][4];
    {
        const uint32_t aQ = sb + (uint32_t)((w * 16 + (l & 15)) * KROW + (l >> 4) * 8) * 2;
        #pragma unroll
        for (int ks = 0; ks < 8; ks++) ldsm4(Aq[ks], aQ + ks * 32);
    }
    __syncthreads();   // all warps done reading Q before K/V overwrite stage 0

    load_kv(sb, t, kh, vh, 0, 0); CP_COMMIT();
    load_kv(sb, t, kh, vh, 1, 1); CP_COMMIT();
    load_kv(sb, t, kh, vh, 2, 2); CP_COMMIT();

    const uint32_t bKrel = (uint32_t)(((l & 7) + ((l >> 4) & 1) * 8) * KROW + ((l >> 3) & 1) * 8) * 2;
    const uint32_t bVrel = (uint32_t)(((l & 7) + ((l >> 4) & 1) * 8) * VROW + ((l >> 3) & 1) * 8) * 2;

    // O: fp16 accumulators, O[nt][0] = half2(c,c+1) row p1, O[nt][1] = row p2
    uint32_t O[16][2];
    #pragma unroll
    for (int n = 0; n < 16; n++) { O[n][0] = 0u; O[n][1] = 0u; }
    float l1 = 0.f, l2 = 0.f;

    int stage = 0;
    for (int j = 0; j < NIT; j++) {
        if (j == 0)            CP_WAIT(2);
        else if (j == NIT - 1) CP_WAIT(0);
        else                   CP_WAIT(1);
        __syncthreads();       // single barrier per iteration

        const uint32_t kbb = sb + (uint32_t)KS_OFF(stage) * 2 + bKrel;
        const uint32_t vbb = sb + (uint32_t)VS_OFF(stage) * 2 + bVrel;

        // ---- two 32-key halves: S (4 fp16 chains, K frags double-buffered) ----
        #pragma unroll
        for (int h = 0; h < 2; h++) {
            uint32_t S16[4][2];
            #pragma unroll
            for (int n = 0; n < 4; n++) { S16[n][0] = 0u; S16[n][1] = 0u; }

            // K fragment double buffer across ks
            uint32_t KA0[4], KA1[4], KB0[4], KB1[4];
            ldsm4(KA0, kbb + (uint32_t)((h * 32) * KROW) * 2);
            ldsm4(KA1, kbb + (uint32_t)((h * 32 + 16) * KROW) * 2);
            #pragma unroll
            for (int ks = 0; ks < 8; ks++) {
                uint32_t* c0 = (ks & 1) ? KB0 : KA0;
                uint32_t* c1 = (ks & 1) ? KB1 : KA1;
                uint32_t* n0 = (ks & 1) ? KA0 : KB0;
                uint32_t* n1 = (ks & 1) ? KA1 : KB1;
                if (ks < 7) {
                    ldsm4(n0, kbb + (uint32_t)((h * 32) * KROW + (ks + 1) * 16) * 2);
                    ldsm4(n1, kbb + (uint32_t)((h * 32 + 16) * KROW + (ks + 1) * 16) * 2);
                }
                mma16816h(S16[0], Aq[ks], c0);
                mma16816h(S16[1], Aq[ks], c0 + 2);
                mma16816h(S16[2], Aq[ks], c1);
                mma16816h(S16[3], Aq[ks], c1 + 2);
            }

            // refill stage (stage+2)%3 after the first S block
            if (h == 0 && j >= 1 && j + 2 < NIT) {
                int ns = stage + 2; if (ns >= 3) ns -= 3;
                load_kv(sb, t, kh, vh, j + 2, ns);
                CP_COMMIT();
            }

            #pragma unroll
            for (int g = 0; g < 2; g++) {       // 16-key groups within the half
                uint32_t P[4];
                {
                    float2 a0 = __half22float2(*(__half2*)&S16[2 * g][0]);     // r1, keys c,c+1
                    float2 a1 = __half22float2(*(__half2*)&S16[2 * g][1]);     // r2
                    float2 b0 = __half22float2(*(__half2*)&S16[2 * g + 1][0]); // r1, keys +8
                    float2 b1 = __half22float2(*(__half2*)&S16[2 * g + 1][1]); // r2
                    float p0 = ex2f(a0.x * EX2SCALE), p1 = ex2f(a0.y * EX2SCALE);
                    float p2 = ex2f(a1.x * EX2SCALE), p3 = ex2f(a1.y * EX2SCALE);
                    float p4 = ex2f(b0.x * EX2SCALE), p5 = ex2f(b0.y * EX2SCALE);
                    float p6 = ex2f(b1.x * EX2SCALE), p7 = ex2f(b1.y * EX2SCALE);
                    P[0] = packh2(p0, p1);
                    P[1] = packh2(p2, p3);
                    P[2] = packh2(p4, p5);
                    P[3] = packh2(p6, p7);
                    l1 += (p0 + p1) + (p4 + p5);
                    l2 += (p2 + p3) + (p6 + p7);
                }
                const int kc = h * 2 + g;       // key-16 chunk index 0..3
                // PV: fp16 accum, double-buffered B prefetch
                uint32_t BfA[4], BfB[4];
                ldsm4(BfA, vbb + (uint32_t)(kc * 16) * 2);
                #pragma unroll
                for (int np = 0; np < 8; np++) {
                    uint32_t* cur = (np & 1) ? BfB : BfA;
                    uint32_t* nxt = (np & 1) ? BfA : BfB;
                    if (np < 7)
                        ldsm4(nxt, vbb + (uint32_t)((np + 1) * 16 * VROW + kc * 16) * 2);
                    mma16816h(O[2 * np],     P, cur);
                    mma16816h(O[2 * np + 1], P, cur + 2);
                }
            }
        }

        if (++stage >= 3) stage = 0;
    }

    // ---- epilogue ----
    l1 += __shfl_xor_sync(0xffffffffu, l1, 1);
    l1 += __shfl_xor_sync(0xffffffffu, l1, 2);
    l2 += __shfl_xor_sync(0xffffffffu, l2, 1);
    l2 += __shfl_xor_sync(0xffffffffu, l2, 2);
    const float i1 = 1.f / l1, i2 = 1.f / l2;

    __syncthreads();                    // all warps done with K/V smem
    float* Osc = (float*)smh;           // [128 c][129] (p fast)
    const int p1 = w * 16 + (l >> 2), p2 = p1 + 8;
    #pragma unroll
    for (int nt = 0; nt < 16; nt++) {
        int c = nt * 8 + 2 * (l & 3);
        float2 lo = __half22float2(*(__half2*)&O[nt][0]);
        float2 hi = __half22float2(*(__half2*)&O[nt][1]);
        Osc[c * 129 + p1]       = lo.x * i1;
        Osc[(c + 1) * 129 + p1] = lo.y * i1;
        Osc[c * 129 + p2]       = hi.x * i2;
        Osc[(c + 1) * 129 + p2] = hi.y * i2;
    }
    __syncthreads();

    const float* qres = g_qres + (size_t)b * CC * HWN + q0;
    float* ob = out + (size_t)b * CC * HWN + q0;
    #pragma unroll
    for (int it = 0; it < 64; it++) {
        int idx = it * 256 + t, c = idx >> 7, p = idx & 127;
        ob[(size_t)c * HWN + p] = Osc[c * 129 + p] + qres[(size_t)c * HWN + p];
    }
}

// ---------------------------------------------------------------------------
extern "C" void kernel_launch(void* const* d_in, const int* in_sizes, int n_in,
                              void* d_out, int out_size)
{
    const float* query = (const float*)d_in[0];
    const float* key   = (const float*)d_in[1];
    const float* value = (const float*)d_in[2];
    const float* Wq    = (const float*)d_in[3];
    const float* bq    = (const float*)d_in[4];
    const float* Wk    = (const float*)d_in[5];
    const float* bk    = (const float*)d_in[6];
    float* out = (float*)d_out;

    cudaFuncSetAttribute(proj_kernel, cudaFuncAttributeMaxDynamicSharedMemorySize, PSM_BYTES);
    cudaFuncSetAttribute(attn_kernel, cudaFuncAttributeMaxDynamicSharedMemorySize, SMEM_BYTES);

    dim3 pgrid(HWN / 128, BN, 3);
    proj_kernel<<<pgrid, 256, PSM_BYTES>>>(query, key, value, Wq, bq, Wk, bk);

    dim3 agrid(HWN / BQ, BN);
    attn_kernel<<<agrid, 256, SMEM_BYTES>>>(out);
}

// round 14
// speedup vs baseline: 1.1448x; 1.0817x over previous
#include <cuda_runtime.h>
#include <cuda_fp16.h>
#include <cstdint>

#define CC   128
#define HWN  4096
#define BN   8
#define BQ   128          // queries per CTA
#define BK   64           // keys per tile
#define NIT  (HWN / BK)   // 64

// scratch
__device__ float  g_qres[(size_t)BN * CC * HWN];  // q proj fp32 [b][c][p] (residual, output layout)
__device__ __half g_qh[(size_t)BN * HWN * CC];    // q proj fp16 [b][p][c]
__device__ __half g_kh[(size_t)BN * HWN * CC];    // k proj fp16 [b][p][c]
__device__ __half g_vh[(size_t)BN * CC * HWN];    // value fp16 [b][c][hw]

// ---------------------------------------------------------------------------
// helpers
// ---------------------------------------------------------------------------
__device__ __forceinline__ uint32_t s2u(const void* p) {
    uint32_t a;
    asm("{ .reg .u64 t; cvta.to.shared.u64 t, %1; cvt.u32.u64 %0, t; }" : "=r"(a) : "l"(p));
    return a;
}
__device__ __forceinline__ void ldsm4(uint32_t* a, uint32_t addr) {
    asm volatile("ldmatrix.sync.aligned.m8n8.x4.shared.b16 {%0,%1,%2,%3},[%4];"
                 : "=r"(a[0]), "=r"(a[1]), "=r"(a[2]), "=r"(a[3]) : "r"(addr));
}
__device__ __forceinline__ void ldsm4t(uint32_t* a, uint32_t addr) {
    asm volatile("ldmatrix.sync.aligned.m8n8.x4.trans.shared.b16 {%0,%1,%2,%3},[%4];"
                 : "=r"(a[0]), "=r"(a[1]), "=r"(a[2]), "=r"(a[3]) : "r"(addr));
}
__device__ __forceinline__ void mma16816(float* d, const uint32_t* a, const uint32_t* b) {
    asm volatile("mma.sync.aligned.m16n8k16.row.col.f32.f16.f16.f32 "
                 "{%0,%1,%2,%3},{%4,%5,%6,%7},{%8,%9},{%0,%1,%2,%3};"
                 : "+f"(d[0]), "+f"(d[1]), "+f"(d[2]), "+f"(d[3])
                 : "r"(a[0]), "r"(a[1]), "r"(a[2]), "r"(a[3]), "r"(b[0]), "r"(b[1]));
}
// fp16-accumulator variant: d = 2 regs (4 halfs)
__device__ __forceinline__ void mma16816h(uint32_t* d, const uint32_t* a, const uint32_t* b) {
    asm volatile("mma.sync.aligned.m16n8k16.row.col.f16.f16.f16.f16 "
                 "{%0,%1},{%2,%3,%4,%5},{%6,%7},{%0,%1};"
                 : "+r"(d[0]), "+r"(d[1])
                 : "r"(a[0]), "r"(a[1]), "r"(a[2]), "r"(a[3]), "r"(b[0]), "r"(b[1]));
}
__device__ __forceinline__ uint32_t packh2(float x, float y) {
    __half2 h = __floats2half2_rn(x, y);
    return *(uint32_t*)&h;
}
// P = ex2(S * scale) on packed half2 — one FMUL-class + one MUFU op for 2 values
__device__ __forceinline__ uint32_t ex2h2(uint32_t s, uint32_t sc) {
    uint32_t m, r;
    asm("mul.rn.f16x2 %0, %1, %2;" : "=r"(m) : "r"(s), "r"(sc));
    asm("ex2.approx.f16x2 %0, %1;" : "=r"(r) : "r"(m));
    return r;
}
__device__ __forceinline__ uint32_t hadd2u(uint32_t a, uint32_t b) {
    uint32_t r;
    asm("add.rn.f16x2 %0, %1, %2;" : "=r"(r) : "r"(a), "r"(b));
    return r;
}

#define CP_A16(dst, src) asm volatile("cp.async.cg.shared.global [%0], [%1], 16;" :: "r"(dst), "l"(src))
#define CP_COMMIT()      asm volatile("cp.async.commit_group;" ::: "memory")
#define CP_WAIT(n)       asm volatile("cp.async.wait_group %0;" :: "n"(n) : "memory")

// ---------------------------------------------------------------------------
// Projection on tensor cores: D[o][p] = sum_c W[o][c] * X[c][p]  (+bias)
// grid (HWN/128, BN, 3), 256 threads. z=0: q proj, z=1: k proj, z=2: V fp32->fp16.
// ---------------------------------------------------------------------------
#define PSM_BYTES (2 * 128 * 136 * 2)   // 69632: Xh + Wh (reused for staging)

__global__ void __launch_bounds__(256) proj_kernel(
    const float* __restrict__ q_img, const float* __restrict__ k_img,
    const float* __restrict__ value,
    const float* __restrict__ Wq, const float* __restrict__ bq,
    const float* __restrict__ Wk, const float* __restrict__ bk)
{
    extern __shared__ __align__(16) char psm[];

    // ---- z == 2: V conversion (pure streaming), overlapped with projections ----
    if (blockIdx.z == 2) {
        const int nth = 32 * 8 * 256;
        int tid = (blockIdx.y * 32 + blockIdx.x) * 256 + threadIdx.x;
        const float4* vin = (const float4*)value;
        __half2* o = (__half2*)g_vh;
        #pragma unroll 4
        for (size_t i = tid; i < (size_t)BN * CC * HWN / 4; i += nth) {
            float4 f = vin[i];
            o[2 * i]     = __floats2half2_rn(f.x, f.y);
            o[2 * i + 1] = __floats2half2_rn(f.z, f.w);
        }
        return;
    }

    __half* Xh  = (__half*)psm;            // [128 c][136] (p fast)
    __half* Wh  = Xh + 128 * 136;          // [128 o][136] (c fast)
    float*  Os  = (float*)psm;             // reuse: [128 o][132] (p fast)
    __half* Osh = (__half*)psm;            // reuse: [128 p][136] (o fast)
    __shared__ float biass[128];

    const bool isQ = (blockIdx.z == 0);
    const float* in   = isQ ? q_img : k_img;
    const float* W    = isQ ? Wq : Wk;
    const float* bias = isQ ? bq : bk;

    const int b  = blockIdx.y;
    const int p0 = blockIdx.x * 128;
    const int t  = threadIdx.x;
    const int w  = t >> 5, l = t & 31;

    const float* inb = in + (size_t)b * CC * HWN;

    // load X [c][p] fp32 -> fp16 smem (rows c, 128 p halfs + pad)
    #pragma unroll
    for (int it = 0; it < 16; it++) {
        int idx = it * 256 + t, c = idx >> 5, f4 = idx & 31;
        float4 v = *(const float4*)(inb + c * HWN + p0 + f4 * 4);
        uint2 h; h.x = packh2(v.x, v.y); h.y = packh2(v.z, v.w);
        *(uint2*)&Xh[c * 136 + f4 * 4] = h;
    }
    // load W [o][c] fp32 -> fp16
    #pragma unroll
    for (int it = 0; it < 16; it++) {
        int idx = it * 256 + t, o = idx >> 5, f4 = idx & 31;
        float4 v = *(const float4*)(W + o * 128 + f4 * 4);
        uint2 h; h.x = packh2(v.x, v.y); h.y = packh2(v.z, v.w);
        *(uint2*)&Wh[o * 136 + f4 * 4] = h;
    }
    if (t < 128) biass[t] = bias[t];
    __syncthreads();

    const uint32_t sb = s2u(psm);
    const uint32_t aW = sb + (uint32_t)(128 * 136 + (w * 16 + (l & 15)) * 136 + (l >> 4) * 8) * 2;
    const uint32_t bX = sb + (uint32_t)((((l & 7) + ((l >> 3) & 1) * 8)) * 136 + ((l >> 4) & 1) * 8) * 2;

    float acc[16][4];
    #pragma unroll
    for (int n = 0; n < 16; n++)
        #pragma unroll
        for (int e = 0; e < 4; e++) acc[n][e] = 0.f;

    #pragma unroll
    for (int ks = 0; ks < 8; ks++) {
        uint32_t A[4];
        ldsm4(A, aW + ks * 32);
        #pragma unroll
        for (int nt2 = 0; nt2 < 8; nt2++) {
            uint32_t Bf[4];
            ldsm4t(Bf, bX + (uint32_t)(ks * 16 * 136 + nt2 * 16) * 2);
            mma16816(acc[2 * nt2],     A, Bf);
            mma16816(acc[2 * nt2 + 1], A, Bf + 2);
        }
    }

    const int o1 = w * 16 + (l >> 2), o2 = o1 + 8;
    const float b1 = biass[o1], b2 = biass[o2];
    #pragma unroll
    for (int n = 0; n < 16; n++) {
        acc[n][0] += b1; acc[n][1] += b1;
        acc[n][2] += b2; acc[n][3] += b2;
    }
    __syncthreads();   // done with Xh/Wh

    if (isQ) {
        // fp32 residual, [o][p] staging -> g_qres coalesced
        #pragma unroll
        for (int n = 0; n < 16; n++) {
            int p = n * 8 + 2 * (l & 3);
            *(float2*)&Os[o1 * 132 + p] = make_float2(acc[n][0], acc[n][1]);
            *(float2*)&Os[o2 * 132 + p] = make_float2(acc[n][2], acc[n][3]);
        }
        __syncthreads();
        float* qres = g_qres + (size_t)b * CC * HWN;
        #pragma unroll
        for (int it = 0; it < 64; it++) {
            int idx = it * 256 + t, o = idx >> 7, p = idx & 127;
            qres[(size_t)o * HWN + p0 + p] = Os[o * 132 + p];
        }
        __syncthreads();
    }

    // fp16 token-major [p][o] staging -> g_qh/g_kh coalesced
    #pragma unroll
    for (int n = 0; n < 16; n++) {
        int p = n * 8 + 2 * (l & 3);
        Osh[p * 136 + o1]       = __float2half(acc[n][0]);
        Osh[(p + 1) * 136 + o1] = __float2half(acc[n][1]);
        Osh[p * 136 + o2]       = __float2half(acc[n][2]);
        Osh[(p + 1) * 136 + o2] = __float2half(acc[n][3]);
    }
    __syncthreads();
    __half* outh = (isQ ? g_qh : g_kh) + (size_t)b * HWN * CC + (size_t)p0 * CC;
    #pragma unroll
    for (int it = 0; it < 32; it++) {
        int idx = it * 256 + t, p = idx >> 6, h2 = idx & 63;
        *(uint32_t*)(outh + (size_t)p * CC + 2 * h2) = *(uint32_t*)&Osh[p * 136 + 2 * h2];
    }
}

// ---------------------------------------------------------------------------
// attn SMEM: 3 stages of {K 64x136, V 128x72} halfs. Q staged in stage 0
// during the prologue only (Q lives in registers afterwards).
// ---------------------------------------------------------------------------
#define KROW 136
#define VROW 72
#define STAGE_HALFS (64 * KROW + 128 * VROW)     // 17920
#define KS_OFF(s)   ((s) * STAGE_HALFS)
#define VS_OFF(s)   ((s) * STAGE_HALFS + 64 * KROW)
#define SMEM_HALFS  (3 * STAGE_HALFS)            // 53760
#define SMEM_BYTES  (SMEM_HALFS * 2)             // 107520

__device__ __forceinline__ void load_kv(uint32_t sb, int t,
                                        const __half* kh, const __half* vh,
                                        int tile, int s)
{
    #pragma unroll
    for (int i = 0; i < 4; i++) {       // K tile: 64 rows x 256B
        int idx = i * 256 + t, r = idx >> 4, c = idx & 15;
        CP_A16(sb + (uint32_t)(KS_OFF(s) + r * KROW) * 2 + c * 16,
               kh + (size_t)(tile * BK + r) * CC + c * 8);
    }
    #pragma unroll
    for (int i = 0; i < 4; i++) {       // V tile: 128 rows(c) x 128B
        int idx = i * 256 + t, r = idx >> 3, c = idx & 7;
        CP_A16(sb + (uint32_t)(VS_OFF(s) + r * VROW) * 2 + c * 16,
               vh + (size_t)r * HWN + tile * BK + c * 8);
    }
}

// exp scale: S * (1/64) * log2(e), applied in half2 before ex2.approx.f16x2
#define EX2SCALE 0.0225421993f

// ---------------------------------------------------------------------------
// Flash attention, fp16 mma.sync. grid (32, 8), 256 threads (8 warps x 16 rows)
// Round-10 structure: Q A-fragments register-resident; 3-stage cp.async, ONE
// barrier/iteration; 32-key halves with 4 independent chains; PV fp16 accum
// with prefetched B-frags. NEW: S in fp16 accum + f16x2 exp (P fragments
// produced directly by mul.f16x2 + ex2.approx.f16x2 — no packing, half MUFU).
// ---------------------------------------------------------------------------
__global__ void __launch_bounds__(256, 2)
attn_kernel(float* __restrict__ out)
{
    extern __shared__ __align__(16) __half smh[];
    const uint32_t sb = s2u(smh);
    const int t = threadIdx.x, w = t >> 5, l = t & 31;
    const int b = blockIdx.y, q0 = blockIdx.x * BQ;

    const __half* qh = g_qh + (size_t)b * HWN * CC + (size_t)q0 * CC;
    const __half* kh = g_kh + (size_t)b * HWN * CC;
    const __half* vh = g_vh + (size_t)b * CC * HWN;

    // ---- prologue: stage Q in stage-0 region, hoist A-fragments to regs ----
    #pragma unroll
    for (int i = 0; i < 8; i++) {       // Q: 128 rows x 256B, row stride KROW halfs
        int idx = i * 256 + t, r = idx >> 4, c = idx & 15;
        CP_A16(sb + (uint32_t)(r * KROW) * 2 + c * 16, qh + (size_t)r * CC + c * 8);
    }
    CP_COMMIT();
    CP_WAIT(0);
    __syncthreads();

    uint32_t Aq[8][4];
    {
        const uint32_t aQ = sb + (uint32_t)((w * 16 + (l & 15)) * KROW + (l >> 4) * 8) * 2;
        #pragma unroll
        for (int ks = 0; ks < 8; ks++) ldsm4(Aq[ks], aQ + ks * 32);
    }
    __syncthreads();   // all warps done reading Q before K/V overwrite stage 0

    load_kv(sb, t, kh, vh, 0, 0); CP_COMMIT();
    load_kv(sb, t, kh, vh, 1, 1); CP_COMMIT();
    load_kv(sb, t, kh, vh, 2, 2); CP_COMMIT();

    const uint32_t bKrel = (uint32_t)(((l & 7) + ((l >> 4) & 1) * 8) * KROW + ((l >> 3) & 1) * 8) * 2;
    const uint32_t bVrel = (uint32_t)(((l & 7) + ((l >> 4) & 1) * 8) * VROW + ((l >> 3) & 1) * 8) * 2;

    // half2 exp scale constant
    const __half2 scH = __float2half2_rn(EX2SCALE);
    const uint32_t sc2 = *(const uint32_t*)&scH;

    // O: fp16 accumulators, O[nt][0] = half2(c,c+1) row p1, O[nt][1] = row p2
    uint32_t O[16][2];
    #pragma unroll
    for (int n = 0; n < 16; n++) { O[n][0] = 0u; O[n][1] = 0u; }
    float l1 = 0.f, l2 = 0.f;

    int stage = 0;
    for (int j = 0; j < NIT; j++) {
        if (j == 0)            CP_WAIT(2);
        else if (j == NIT - 1) CP_WAIT(0);
        else                   CP_WAIT(1);
        __syncthreads();       // single barrier per iteration

        const uint32_t kbb = sb + (uint32_t)KS_OFF(stage) * 2 + bKrel;
        const uint32_t vbb = sb + (uint32_t)VS_OFF(stage) * 2 + bVrel;

        // ---- two 32-key halves: S (4 fp16 chains) -> f16x2 exp -> PV ----
        #pragma unroll
        for (int h = 0; h < 2; h++) {
            uint32_t S16[4][2];
            #pragma unroll
            for (int n = 0; n < 4; n++) { S16[n][0] = 0u; S16[n][1] = 0u; }

            #pragma unroll
            for (int ks = 0; ks < 8; ks++) {
                uint32_t Bf0[4], Bf1[4];
                ldsm4(Bf0, kbb + (uint32_t)((h * 32) * KROW + ks * 16) * 2);
                ldsm4(Bf1, kbb + (uint32_t)((h * 32 + 16) * KROW + ks * 16) * 2);
                mma16816h(S16[0], Aq[ks], Bf0);
                mma16816h(S16[1], Aq[ks], Bf0 + 2);
                mma16816h(S16[2], Aq[ks], Bf1);
                mma16816h(S16[3], Aq[ks], Bf1 + 2);
            }

            // refill stage (stage+2)%3 after the first S block
            if (h == 0 && j >= 1 && j + 2 < NIT) {
                int ns = stage + 2; if (ns >= 3) ns -= 3;
                load_kv(sb, t, kh, vh, j + 2, ns);
                CP_COMMIT();
            }

            #pragma unroll
            for (int g = 0; g < 2; g++) {       // 16-key groups within the half
                // P fragments directly from half2 S: mul.f16x2 + ex2.f16x2
                uint32_t P[4];
                P[0] = ex2h2(S16[2 * g][0],     sc2);   // r1, keys k..k+7 pair
                P[1] = ex2h2(S16[2 * g][1],     sc2);   // r2
                P[2] = ex2h2(S16[2 * g + 1][0], sc2);   // r1, keys +8
                P[3] = ex2h2(S16[2 * g + 1][1], sc2);   // r2
                {
                    uint32_t t1 = hadd2u(P[0], P[2]);   // r1 pair sums
                    uint32_t t2 = hadd2u(P[1], P[3]);   // r2 pair sums
                    float2 f1 = __half22float2(*(__half2*)&t1);
                    float2 f2 = __half22float2(*(__half2*)&t2);
                    l1 += f1.x + f1.y;
                    l2 += f2.x + f2.y;
                }
                const int kc = h * 2 + g;       // key-16 chunk index 0..3
                // PV: fp16 accum, double-buffered B prefetch
                uint32_t BfA[4], BfB[4];
                ldsm4(BfA, vbb + (uint32_t)(kc * 16) * 2);
                #pragma unroll
                for (int np = 0; np < 8; np++) {
                    uint32_t* cur = (np & 1) ? BfB : BfA;
                    uint32_t* nxt = (np & 1) ? BfA : BfB;
                    if (np < 7)
                        ldsm4(nxt, vbb + (uint32_t)((np + 1) * 16 * VROW + kc * 16) * 2);
                    mma16816h(O[2 * np],     P, cur);
                    mma16816h(O[2 * np + 1], P, cur + 2);
                }
            }
        }

        if (++stage >= 3) stage = 0;
    }

    // ---- epilogue ----
    l1 += __shfl_xor_sync(0xffffffffu, l1, 1);
    l1 += __shfl_xor_sync(0xffffffffu, l1, 2);
    l2 += __shfl_xor_sync(0xffffffffu, l2, 1);
    l2 += __shfl_xor_sync(0xffffffffu, l2, 2);
    const float i1 = 1.f / l1, i2 = 1.f / l2;

    __syncthreads();                    // all warps done with K/V smem
    float* Osc = (float*)smh;           // [128 c][129] (p fast)
    const int p1 = w * 16 + (l >> 2), p2 = p1 + 8;
    #pragma unroll
    for (int nt = 0; nt < 16; nt++) {
        int c = nt * 8 + 2 * (l & 3);
        float2 lo = __half22float2(*(__half2*)&O[nt][0]);
        float2 hi = __half22float2(*(__half2*)&O[nt][1]);
        Osc[c * 129 + p1]       = lo.x * i1;
        Osc[(c + 1) * 129 + p1] = lo.y * i1;
        Osc[c * 129 + p2]       = hi.x * i2;
        Osc[(c + 1) * 129 + p2] = hi.y * i2;
    }
    __syncthreads();

    const float* qres = g_qres + (size_t)b * CC * HWN + q0;
    float* ob = out + (size_t)b * CC * HWN + q0;
    #pragma unroll
    for (int it = 0; it < 64; it++) {
        int idx = it * 256 + t, c = idx >> 7, p = idx & 127;
        ob[(size_t)c * HWN + p] = Osc[c * 129 + p] + qres[(size_t)c * HWN + p];
    }
}

// ---------------------------------------------------------------------------
extern "C" void kernel_launch(void* const* d_in, const int* in_sizes, int n_in,
                              void* d_out, int out_size)
{
    const float* query = (const float*)d_in[0];
    const float* key   = (const float*)d_in[1];
    const float* value = (const float*)d_in[2];
    const float* Wq    = (const float*)d_in[3];
    const float* bq    = (const float*)d_in[4];
    const float* Wk    = (const float*)d_in[5];
    const float* bk    = (const float*)d_in[6];
    float* out = (float*)d_out;

    cudaFuncSetAttribute(proj_kernel, cudaFuncAttributeMaxDynamicSharedMemorySize, PSM_BYTES);
    cudaFuncSetAttribute(attn_kernel, cudaFuncAttributeMaxDynamicSharedMemorySize, SMEM_BYTES);

    dim3 pgrid(HWN / 128, BN, 3);
    proj_kernel<<<pgrid, 256, PSM_BYTES>>>(query, key, value, Wq, bq, Wk, bk);

    dim3 agrid(HWN / BQ, BN);
    attn_kernel<<<agrid, 256, SMEM_BYTES>>>(out);
}

// round 15
// speedup vs baseline: 1.1478x; 1.0027x over previous
#include <cuda_runtime.h>
#include <cuda_fp16.h>
#include <cstdint>

#define CC   128
#define HWN  4096
#define BN   8
#define BQ   128          // queries per CTA
#define BK   64           // keys per tile
#define NIT  (HWN / BK)   // 64

// scratch
__device__ float  g_qres[(size_t)BN * CC * HWN];  // q proj fp32 [b][c][p] (residual, output layout)
__device__ __half g_qh[(size_t)BN * HWN * CC];    // q proj fp16 [b][p][c]
__device__ __half g_kh[(size_t)BN * HWN * CC];    // k proj fp16 [b][p][c]
__device__ __half g_vh[(size_t)BN * CC * HWN];    // value fp16 [b][c][hw]

// ---------------------------------------------------------------------------
// helpers
// ---------------------------------------------------------------------------
__device__ __forceinline__ uint32_t s2u(const void* p) {
    uint32_t a;
    asm("{ .reg .u64 t; cvta.to.shared.u64 t, %1; cvt.u32.u64 %0, t; }" : "=r"(a) : "l"(p));
    return a;
}
__device__ __forceinline__ void ldsm4(uint32_t* a, uint32_t addr) {
    asm volatile("ldmatrix.sync.aligned.m8n8.x4.shared.b16 {%0,%1,%2,%3},[%4];"
                 : "=r"(a[0]), "=r"(a[1]), "=r"(a[2]), "=r"(a[3]) : "r"(addr));
}
__device__ __forceinline__ void ldsm4t(uint32_t* a, uint32_t addr) {
    asm volatile("ldmatrix.sync.aligned.m8n8.x4.trans.shared.b16 {%0,%1,%2,%3},[%4];"
                 : "=r"(a[0]), "=r"(a[1]), "=r"(a[2]), "=r"(a[3]) : "r"(addr));
}
__device__ __forceinline__ void mma16816(float* d, const uint32_t* a, const uint32_t* b) {
    asm volatile("mma.sync.aligned.m16n8k16.row.col.f32.f16.f16.f32 "
                 "{%0,%1,%2,%3},{%4,%5,%6,%7},{%8,%9},{%0,%1,%2,%3};"
                 : "+f"(d[0]), "+f"(d[1]), "+f"(d[2]), "+f"(d[3])
                 : "r"(a[0]), "r"(a[1]), "r"(a[2]), "r"(a[3]), "r"(b[0]), "r"(b[1]));
}
// fp16-accumulator variant: d = 2 regs (4 halfs)
__device__ __forceinline__ void mma16816h(uint32_t* d, const uint32_t* a, const uint32_t* b) {
    asm volatile("mma.sync.aligned.m16n8k16.row.col.f16.f16.f16.f16 "
                 "{%0,%1},{%2,%3,%4,%5},{%6,%7},{%0,%1};"
                 : "+r"(d[0]), "+r"(d[1])
                 : "r"(a[0]), "r"(a[1]), "r"(a[2]), "r"(a[3]), "r"(b[0]), "r"(b[1]));
}
__device__ __forceinline__ uint32_t packh2(float x, float y) {
    __half2 h = __floats2half2_rn(x, y);
    return *(uint32_t*)&h;
}
// P = ex2(S * scale) on packed half2 — one FMUL-class + one MUFU op for 2 values
__device__ __forceinline__ uint32_t ex2h2(uint32_t s, uint32_t sc) {
    uint32_t m, r;
    asm("mul.rn.f16x2 %0, %1, %2;" : "=r"(m) : "r"(s), "r"(sc));
    asm("ex2.approx.f16x2 %0, %1;" : "=r"(r) : "r"(m));
    return r;
}

#define CP_A16(dst, src) asm volatile("cp.async.cg.shared.global [%0], [%1], 16;" :: "r"(dst), "l"(src))
#define CP_COMMIT()      asm volatile("cp.async.commit_group;" ::: "memory")
#define CP_WAIT(n)       asm volatile("cp.async.wait_group %0;" :: "n"(n) : "memory")

// ---------------------------------------------------------------------------
// Projection on tensor cores: D[o][p] = sum_c W[o][c] * X[c][p]  (+bias)
// grid (HWN/64, BN, 3), 256 threads. z=0: q proj, z=1: k proj, z=2: V fp32->fp16.
// p-tile = 64 (3 CTAs/SM target for latency hiding).
// ---------------------------------------------------------------------------
#define XROW 72
#define PSM_BYTES (128 * XROW * 2 + 128 * 136 * 2)   // 53248: Xh + Wh

__global__ void __launch_bounds__(256, 3) proj_kernel(
    const float* __restrict__ q_img, const float* __restrict__ k_img,
    const float* __restrict__ value,
    const float* __restrict__ Wq, const float* __restrict__ bq,
    const float* __restrict__ Wk, const float* __restrict__ bk)
{
    extern __shared__ __align__(16) char psm[];

    // ---- z == 2: V conversion (pure streaming), overlapped with projections ----
    if (blockIdx.z == 2) {
        const int nth = 64 * 8 * 256;
        int tid = (blockIdx.y * 64 + blockIdx.x) * 256 + threadIdx.x;
        const float4* vin = (const float4*)value;
        __half2* o = (__half2*)g_vh;
        #pragma unroll 4
        for (size_t i = tid; i < (size_t)BN * CC * HWN / 4; i += nth) {
            float4 f = vin[i];
            o[2 * i]     = __floats2half2_rn(f.x, f.y);
            o[2 * i + 1] = __floats2half2_rn(f.z, f.w);
        }
        return;
    }

    __half* Xh  = (__half*)psm;              // [128 c][72]  (p fast, 64 + pad)
    __half* Wh  = Xh + 128 * XROW;           // [128 o][136] (c fast)
    float*  Os  = (float*)psm;               // reuse: [128 o][68] (p fast)
    __half* Osh = (__half*)psm;              // reuse: [64 p][136] (o fast)
    __shared__ float biass[128];

    const bool isQ = (blockIdx.z == 0);
    const float* in   = isQ ? q_img : k_img;
    const float* W    = isQ ? Wq : Wk;
    const float* bias = isQ ? bq : bk;

    const int b  = blockIdx.y;
    const int p0 = blockIdx.x * 64;
    const int t  = threadIdx.x;
    const int w  = t >> 5, l = t & 31;

    const float* inb = in + (size_t)b * CC * HWN;

    // load X [c][p] fp32 -> fp16 smem (128 c x 64 p)
    #pragma unroll
    for (int it = 0; it < 8; it++) {
        int idx = it * 256 + t, c = idx >> 4, f4 = idx & 15;
        float4 v = *(const float4*)(inb + c * HWN + p0 + f4 * 4);
        uint2 h; h.x = packh2(v.x, v.y); h.y = packh2(v.z, v.w);
        *(uint2*)&Xh[c * XROW + f4 * 4] = h;
    }
    // load W [o][c] fp32 -> fp16
    #pragma unroll
    for (int it = 0; it < 16; it++) {
        int idx = it * 256 + t, o = idx >> 5, f4 = idx & 31;
        float4 v = *(const float4*)(W + o * 128 + f4 * 4);
        uint2 h; h.x = packh2(v.x, v.y); h.y = packh2(v.z, v.w);
        *(uint2*)&Wh[o * 136 + f4 * 4] = h;
    }
    if (t < 128) biass[t] = bias[t];
    __syncthreads();

    const uint32_t sb = s2u(psm);
    const uint32_t aW = sb + (uint32_t)(128 * XROW + (w * 16 + (l & 15)) * 136 + (l >> 4) * 8) * 2;
    const uint32_t bX = sb + (uint32_t)((((l & 7) + ((l >> 3) & 1) * 8)) * XROW + ((l >> 4) & 1) * 8) * 2;

    float acc[8][4];
    #pragma unroll
    for (int n = 0; n < 8; n++)
        #pragma unroll
        for (int e = 0; e < 4; e++) acc[n][e] = 0.f;

    #pragma unroll
    for (int ks = 0; ks < 8; ks++) {
        uint32_t A[4];
        ldsm4(A, aW + ks * 32);
        #pragma unroll
        for (int nt2 = 0; nt2 < 4; nt2++) {
            uint32_t Bf[4];
            ldsm4t(Bf, bX + (uint32_t)(ks * 16 * XROW + nt2 * 16) * 2);
            mma16816(acc[2 * nt2],     A, Bf);
            mma16816(acc[2 * nt2 + 1], A, Bf + 2);
        }
    }

    const int o1 = w * 16 + (l >> 2), o2 = o1 + 8;
    const float b1 = biass[o1], b2 = biass[o2];
    #pragma unroll
    for (int n = 0; n < 8; n++) {
        acc[n][0] += b1; acc[n][1] += b1;
        acc[n][2] += b2; acc[n][3] += b2;
    }
    __syncthreads();   // done with Xh/Wh

    if (isQ) {
        // fp32 residual, [o][p] staging -> g_qres coalesced
        #pragma unroll
        for (int n = 0; n < 8; n++) {
            int p = n * 8 + 2 * (l & 3);
            *(float2*)&Os[o1 * 68 + p] = make_float2(acc[n][0], acc[n][1]);
            *(float2*)&Os[o2 * 68 + p] = make_float2(acc[n][2], acc[n][3]);
        }
        __syncthreads();
        float* qres = g_qres + (size_t)b * CC * HWN;
        #pragma unroll
        for (int it = 0; it < 32; it++) {
            int idx = it * 256 + t, o = idx >> 6, p = idx & 63;
            qres[(size_t)o * HWN + p0 + p] = Os[o * 68 + p];
        }
        __syncthreads();
    }

    // fp16 token-major [p][o] staging -> g_qh/g_kh coalesced
    #pragma unroll
    for (int n = 0; n < 8; n++) {
        int p = n * 8 + 2 * (l & 3);
        Osh[p * 136 + o1]       = __float2half(acc[n][0]);
        Osh[(p + 1) * 136 + o1] = __float2half(acc[n][1]);
        Osh[p * 136 + o2]       = __float2half(acc[n][2]);
        Osh[(p + 1) * 136 + o2] = __float2half(acc[n][3]);
    }
    __syncthreads();
    __half* outh = (isQ ? g_qh : g_kh) + (size_t)b * HWN * CC + (size_t)p0 * CC;
    #pragma unroll
    for (int it = 0; it < 16; it++) {
        int idx = it * 256 + t, p = idx >> 6, h2 = idx & 63;
        *(uint32_t*)(outh + (size_t)p * CC + 2 * h2) = *(uint32_t*)&Osh[p * 136 + 2 * h2];
    }
}

// ---------------------------------------------------------------------------
// attn SMEM: 3 stages of {K 64x136, V 128x72} halfs. Q staged in stage 0
// during the prologue only (Q lives in registers afterwards).
// ---------------------------------------------------------------------------
#define KROW 136
#define VROW 72
#define STAGE_HALFS (64 * KROW + 128 * VROW)     // 17920
#define KS_OFF(s)   ((s) * STAGE_HALFS)
#define VS_OFF(s)   ((s) * STAGE_HALFS + 64 * KROW)
#define SMEM_HALFS  (3 * STAGE_HALFS)            // 53760
#define SMEM_BYTES  (SMEM_HALFS * 2)             // 107520

__device__ __forceinline__ void load_kv(uint32_t sb, int t,
                                        const __half* kh, const __half* vh,
                                        int tile, int s)
{
    #pragma unroll
    for (int i = 0; i < 4; i++) {       // K tile: 64 rows x 256B
        int idx = i * 256 + t, r = idx >> 4, c = idx & 15;
        CP_A16(sb + (uint32_t)(KS_OFF(s) + r * KROW) * 2 + c * 16,
               kh + (size_t)(tile * BK + r) * CC + c * 8);
    }
    #pragma unroll
    for (int i = 0; i < 4; i++) {       // V tile: 128 rows(c) x 128B
        int idx = i * 256 + t, r = idx >> 3, c = idx & 7;
        CP_A16(sb + (uint32_t)(VS_OFF(s) + r * VROW) * 2 + c * 16,
               vh + (size_t)r * HWN + tile * BK + c * 8);
    }
}

// exp scale: S * (1/64) * log2(e), applied in half2 before ex2.approx.f16x2
#define EX2SCALE 0.0225421993f
#define ONESH2   0x3C003C00u   // half2(1.0, 1.0)

// ---------------------------------------------------------------------------
// Flash attention, fp16 mma.sync. grid (32, 8), 256 threads (8 warps x 16 rows)
// Q A-fragments register-resident; 3-stage cp.async, ONE barrier/iteration;
// 32-key halves, fp16 S + f16x2 exp; PV fp16 accum with prefetched B-frags.
// NEW: l computed by a dedicated fp32-accum MMA vs constant-ones B fragment
// (tensor cross-lane reduction; no ALU l-chain, no epilogue shuffles).
// ---------------------------------------------------------------------------
__global__ void __launch_bounds__(256, 2)
attn_kernel(float* __restrict__ out)
{
    extern __shared__ __align__(16) __half smh[];
    const uint32_t sb = s2u(smh);
    const int t = threadIdx.x, w = t >> 5, l = t & 31;
    const int b = blockIdx.y, q0 = blockIdx.x * BQ;

    const __half* qh = g_qh + (size_t)b * HWN * CC + (size_t)q0 * CC;
    const __half* kh = g_kh + (size_t)b * HWN * CC;
    const __half* vh = g_vh + (size_t)b * CC * HWN;

    // ---- prologue: stage Q in stage-0 region, hoist A-fragments to regs ----
    #pragma unroll
    for (int i = 0; i < 8; i++) {       // Q: 128 rows x 256B, row stride KROW halfs
        int idx = i * 256 + t, r = idx >> 4, c = idx & 15;
        CP_A16(sb + (uint32_t)(r * KROW) * 2 + c * 16, qh + (size_t)r * CC + c * 8);
    }
    CP_COMMIT();
    CP_WAIT(0);
    __syncthreads();

    uint32_t Aq[8][4];
    {
        const uint32_t aQ = sb + (uint32_t)((w * 16 + (l & 15)) * KROW + (l >> 4) * 8) * 2;
        #pragma unroll
        for (int ks = 0; ks < 8; ks++) ldsm4(Aq[ks], aQ + ks * 32);
    }
    __syncthreads();   // all warps done reading Q before K/V overwrite stage 0

    load_kv(sb, t, kh, vh, 0, 0); CP_COMMIT();
    load_kv(sb, t, kh, vh, 1, 1); CP_COMMIT();
    load_kv(sb, t, kh, vh, 2, 2); CP_COMMIT();

    const uint32_t bKrel = (uint32_t)(((l & 7) + ((l >> 4) & 1) * 8) * KROW + ((l >> 3) & 1) * 8) * 2;
    const uint32_t bVrel = (uint32_t)(((l & 7) + ((l >> 4) & 1) * 8) * VROW + ((l >> 3) & 1) * 8) * 2;

    // half2 exp scale constant + ones B fragment for l-MMA
    const __half2 scH = __float2half2_rn(EX2SCALE);
    const uint32_t sc2 = *(const uint32_t*)&scH;
    const uint32_t Bones[2] = {ONESH2, ONESH2};

    // O: fp16 accumulators; Ol: fp32 l accumulator (rows p1/p2 sums)
    uint32_t O[16][2];
    #pragma unroll
    for (int n = 0; n < 16; n++) { O[n][0] = 0u; O[n][1] = 0u; }
    float Ol[4] = {0.f, 0.f, 0.f, 0.f};

    int stage = 0;
    for (int j = 0; j < NIT; j++) {
        if (j == 0)            CP_WAIT(2);
        else if (j == NIT - 1) CP_WAIT(0);
        else                   CP_WAIT(1);
        __syncthreads();       // single barrier per iteration

        const uint32_t kbb = sb + (uint32_t)KS_OFF(stage) * 2 + bKrel;
        const uint32_t vbb = sb + (uint32_t)VS_OFF(stage) * 2 + bVrel;

        // ---- two 32-key halves: S (4 fp16 chains) -> f16x2 exp -> PV ----
        #pragma unroll
        for (int h = 0; h < 2; h++) {
            uint32_t S16[4][2];
            #pragma unroll
            for (int n = 0; n < 4; n++) { S16[n][0] = 0u; S16[n][1] = 0u; }

            #pragma unroll
            for (int ks = 0; ks < 8; ks++) {
                uint32_t Bf0[4], Bf1[4];
                ldsm4(Bf0, kbb + (uint32_t)((h * 32) * KROW + ks * 16) * 2);
                ldsm4(Bf1, kbb + (uint32_t)((h * 32 + 16) * KROW + ks * 16) * 2);
                mma16816h(S16[0], Aq[ks], Bf0);
                mma16816h(S16[1], Aq[ks], Bf0 + 2);
                mma16816h(S16[2], Aq[ks], Bf1);
                mma16816h(S16[3], Aq[ks], Bf1 + 2);
            }

            // refill stage (stage+2)%3 after the first S block
            if (h == 0 && j >= 1 && j + 2 < NIT) {
                int ns = stage + 2; if (ns >= 3) ns -= 3;
                load_kv(sb, t, kh, vh, j + 2, ns);
                CP_COMMIT();
            }

            #pragma unroll
            for (int g = 0; g < 2; g++) {       // 16-key groups within the half
                // P fragments directly from half2 S: mul.f16x2 + ex2.f16x2
                uint32_t P[4];
                P[0] = ex2h2(S16[2 * g][0],     sc2);   // r1, keys k..k+7 pair
                P[1] = ex2h2(S16[2 * g][1],     sc2);   // r2
                P[2] = ex2h2(S16[2 * g + 1][0], sc2);   // r1, keys +8
                P[3] = ex2h2(S16[2 * g + 1][1], sc2);   // r2
                // l accumulation on the tensor pipe (fp32, exact row sums)
                mma16816(Ol, P, Bones);
                const int kc = h * 2 + g;       // key-16 chunk index 0..3
                // PV: fp16 accum, double-buffered B prefetch
                uint32_t BfA[4], BfB[4];
                ldsm4(BfA, vbb + (uint32_t)(kc * 16) * 2);
                #pragma unroll
                for (int np = 0; np < 8; np++) {
                    uint32_t* cur = (np & 1) ? BfB : BfA;
                    uint32_t* nxt = (np & 1) ? BfA : BfB;
                    if (np < 7)
                        ldsm4(nxt, vbb + (uint32_t)((np + 1) * 16 * VROW + kc * 16) * 2);
                    mma16816h(O[2 * np],     P, cur);
                    mma16816h(O[2 * np + 1], P, cur + 2);
                }
            }
        }

        if (++stage >= 3) stage = 0;
    }

    // ---- epilogue (l already cross-lane reduced by the ones-MMA) ----
    const float i1 = 1.f / Ol[0], i2 = 1.f / Ol[2];

    __syncthreads();                    // all warps done with K/V smem
    float* Osc = (float*)smh;           // [128 c][129] (p fast)
    const int p1 = w * 16 + (l >> 2), p2 = p1 + 8;
    #pragma unroll
    for (int nt = 0; nt < 16; nt++) {
        int c = nt * 8 + 2 * (l & 3);
        float2 lo = __half22float2(*(__half2*)&O[nt][0]);
        float2 hi = __half22float2(*(__half2*)&O[nt][1]);
        Osc[c * 129 + p1]       = lo.x * i1;
        Osc[(c + 1) * 129 + p1] = lo.y * i1;
        Osc[c * 129 + p2]       = hi.x * i2;
        Osc[(c + 1) * 129 + p2] = hi.y * i2;
    }
    __syncthreads();

    const float* qres = g_qres + (size_t)b * CC * HWN + q0;
    float* ob = out + (size_t)b * CC * HWN + q0;
    #pragma unroll
    for (int it = 0; it < 64; it++) {
        int idx = it * 256 + t, c = idx >> 7, p = idx & 127;
        ob[(size_t)c * HWN + p] = Osc[c * 129 + p] + qres[(size_t)c * HWN + p];
    }
}

// ---------------------------------------------------------------------------
extern "C" void kernel_launch(void* const* d_in, const int* in_sizes, int n_in,
                              void* d_out, int out_size)
{
    const float* query = (const float*)d_in[0];
    const float* key   = (const float*)d_in[1];
    const float* value = (const float*)d_in[2];
    const float* Wq    = (const float*)d_in[3];
    const float* bq    = (const float*)d_in[4];
    const float* Wk    = (const float*)d_in[5];
    const float* bk    = (const float*)d_in[6];
    float* out = (float*)d_out;

    cudaFuncSetAttribute(proj_kernel, cudaFuncAttributeMaxDynamicSharedMemorySize, PSM_BYTES);
    cudaFuncSetAttribute(attn_kernel, cudaFuncAttributeMaxDynamicSharedMemorySize, SMEM_BYTES);

    dim3 pgrid(HWN / 64, BN, 3);
    proj_kernel<<<pgrid, 256, PSM_BYTES>>>(query, key, value, Wq, bq, Wk, bk);

    dim3 agrid(HWN / BQ, BN);
    attn_kernel<<<agrid, 256, SMEM_BYTES>>>(out);
}